// round 15
// baseline (speedup 1.0000x reference)
#include <cuda_runtime.h>
#include <math.h>
#include <stdint.h>

// Problem constants
#define TT 500
#define BB 16
#define SS 32          // 2*B sequences
#define FF 512
#define HH 1024
#define GG 2048        // 2*H gates
#define MM 16000       // SS*TT rows
#define NC 128         // persistent CTAs (2 groups of 64)
#define NSTAT 125      // stats partial blocks (one per gemm row-tile)
#define CLS 4          // cluster size for h multicast
#define QB 16384       // 64KB group h / 4 slices

// GEMM tiling
#define BM 128
#define BN 128
#define BK 32
#define MP 132
#define KP 36

// ---------------- device scratch ----------------
__device__ float    g_w[(size_t)SS * TT * GG];
__device__ float    g_hs0[(size_t)SS * TT * HH];
__device__ float    g_hT2[2][2][1024 * 16];         // [group][slot][k][16 seq]
__device__ float    g_psum[NSTAT * GG];
__device__ float    g_psumsq[NSTAT * GG];
__device__ float    g_scale[GG];
__device__ float    g_shift[GG];
__device__ unsigned g_bars[64];                     // per-group counters, 128B apart

// ---------------- reset ----------------
__global__ void reset_kernel() {
    int idx = blockIdx.x * blockDim.x + threadIdx.x;
    if (idx < 2 * 2 * 1024 * 16) ((float*)g_hT2)[idx] = 0.0f;
    if (idx < 64) g_bars[idx] = 0u;
}

// ---------------- tf32 helpers ----------------
__device__ __forceinline__ uint2 split_tf32(float v) {
    uint32_t hi;
    asm("cvt.rna.tf32.f32 %0, %1;" : "=r"(hi) : "f"(v));
    float r = v - __uint_as_float(hi);
    uint32_t lo;
    asm("cvt.rna.tf32.f32 %0, %1;" : "=r"(lo) : "f"(r));
    return make_uint2(hi, lo);
}

__device__ __forceinline__ void mma_tf32(float c[4],
                                         uint32_t a0, uint32_t a1, uint32_t a2, uint32_t a3,
                                         uint32_t b0, uint32_t b1) {
    asm volatile(
        "mma.sync.aligned.m16n8k8.row.col.f32.tf32.tf32.f32 "
        "{%0,%1,%2,%3}, {%4,%5,%6,%7}, {%8,%9}, {%0,%1,%2,%3};"
        : "+f"(c[0]), "+f"(c[1]), "+f"(c[2]), "+f"(c[3])
        : "r"(a0), "r"(a1), "r"(a2), "r"(a3), "r"(b0), "r"(b1));
}

// ---------------- f32x2 helpers ----------------
__device__ __forceinline__ void ffma2(unsigned long long& c, unsigned long long a,
                                      unsigned long long b) {
    asm("fma.rn.f32x2 %0, %1, %2, %0;" : "+l"(c) : "l"(a), "l"(b));
}
__device__ __forceinline__ unsigned long long bcast2(float x) {
    unsigned long long r;
    unsigned xi = __float_as_uint(x);
    asm("mov.b64 %0, {%1, %1};" : "=l"(r) : "r"(xi));
    return r;
}
__device__ __forceinline__ float2 unpack2(unsigned long long v) {
    unsigned lo, hi;
    asm("mov.b64 {%0, %1}, %2;" : "=r"(lo), "=r"(hi) : "l"(v));
    return make_float2(__uint_as_float(lo), __uint_as_float(hi));
}

__device__ __forceinline__ uint32_t smem_u32(const void* p) {
    uint32_t a;
    asm("{ .reg .u64 t; cvta.to.shared.u64 t, %1; cvt.u32.u64 %0, t; }" : "=r"(a) : "l"(p));
    return a;
}

__device__ __forceinline__ void mbar_wait(uint32_t mbar, uint32_t parity) {
    asm volatile(
        "{\n\t.reg .pred P;\n\t"
        "W%=:\n\t"
        "mbarrier.try_wait.parity.acquire.cta.shared::cta.b64 P, [%0], %1;\n\t"
        "@!P bra W%=;\n\t}"
        :: "r"(mbar), "r"(parity) : "memory");
}

// ---------------- tensor-core GEMM (3xTF32) + fused stats epilogue ----------------
template <int K, int LAYER>
__global__ void __launch_bounds__(256) gemm_tc(const float* __restrict__ X,
                                               const float* __restrict__ Wt) {
    extern __shared__ uint2 sm2[];
    uint2* sA = sm2;
    uint2* sB = sm2 + 2 * BK * MP;

    const int tid = threadIdx.x;
    const int m0 = blockIdx.y * BM;
    const int n0 = blockIdx.x * BN;

    const int lr = tid >> 1;
    const int kq = (tid & 1) * 16;

    const int m = m0 + lr;
    const int s = m / TT;
    const int t = m - s * TT;
    const float* aLo;
    const float* aHi = nullptr;
    if (LAYER == 0) {
        aLo = (s < BB) ? X + (size_t)(s * TT + t) * FF
                       : X + (size_t)((s - BB) * TT + (TT - 1 - t)) * FF;
    } else {
        const int rowLo = (s < BB) ? (s * TT + t) : ((s - BB) * TT + (TT - 1 - t));
        const int rowHi = (s < BB) ? ((s + BB) * TT + (TT - 1 - t)) : (s * TT + t);
        aLo = g_hs0 + (size_t)rowLo * HH;
        aHi = g_hs0 + (size_t)rowHi * HH - HH;
    }
    const float* bPtr = Wt + (size_t)(n0 + lr) * K;

    const int wid = tid >> 5, lane = tid & 31;
    const int wm = wid >> 2, wn = wid & 3;
    const int g8 = lane >> 2, t4 = lane & 3;

    float c[4][4][4];
#pragma unroll
    for (int i = 0; i < 4; i++)
#pragma unroll
        for (int j = 0; j < 4; j++)
#pragma unroll
            for (int e = 0; e < 4; e++) c[i][j][e] = 0.0f;

    float4 pa[4], pb[4];
    const int NKB = K / BK;

    {
#pragma unroll
        for (int cI = 0; cI < 4; cI++) {
            const int kk = kq + cI * 4;
            const float* ap = (LAYER == 0) ? aLo : ((kk < HH) ? aLo : aHi);
            pa[cI] = *(const float4*)(ap + kk);
            pb[cI] = *(const float4*)(bPtr + kk);
        }
        uint2* sAb = sA;
        uint2* sBb = sB;
#pragma unroll
        for (int cI = 0; cI < 4; cI++) {
            const float va[4] = {pa[cI].x, pa[cI].y, pa[cI].z, pa[cI].w};
            const float vb[4] = {pb[cI].x, pb[cI].y, pb[cI].z, pb[cI].w};
#pragma unroll
            for (int e = 0; e < 4; e++)
                sAb[(kq + cI * 4 + e) * MP + lr] = split_tf32(va[e]);
            const uint2 s0 = split_tf32(vb[0]), s1 = split_tf32(vb[1]);
            const uint2 s2 = split_tf32(vb[2]), s3 = split_tf32(vb[3]);
            *(uint4*)&sBb[lr * KP + kq + cI * 4]     = make_uint4(s0.x, s0.y, s1.x, s1.y);
            *(uint4*)&sBb[lr * KP + kq + cI * 4 + 2] = make_uint4(s2.x, s2.y, s3.x, s3.y);
        }
    }
    __syncthreads();

    for (int kb = 0; kb < NKB; kb++) {
        if (kb + 1 < NKB) {
            const int k0 = (kb + 1) * BK;
#pragma unroll
            for (int cI = 0; cI < 4; cI++) {
                const int kk = k0 + kq + cI * 4;
                const float* ap = (LAYER == 0) ? aLo : ((kk < HH) ? aLo : aHi);
                pa[cI] = *(const float4*)(ap + kk);
                pb[cI] = *(const float4*)(bPtr + kk);
            }
        }

        {
            uint2* sAb = sA + (kb & 1) * BK * MP;
            uint2* sBb = sB + (kb & 1) * BN * KP;
#pragma unroll
            for (int k8 = 0; k8 < 4; k8++) {
                const int kk = k8 * 8;
                uint2 af[4][4];
#pragma unroll
                for (int mt = 0; mt < 4; mt++) {
                    const int mb = wm * 64 + mt * 16 + g8;
                    af[mt][0] = sAb[(kk + t4) * MP + mb];
                    af[mt][1] = sAb[(kk + t4) * MP + mb + 8];
                    af[mt][2] = sAb[(kk + t4 + 4) * MP + mb];
                    af[mt][3] = sAb[(kk + t4 + 4) * MP + mb + 8];
                }
                uint2 bf[4][2];
#pragma unroll
                for (int nt = 0; nt < 4; nt++) {
                    const int nb = wn * 32 + nt * 8 + g8;
                    bf[nt][0] = sBb[nb * KP + kk + t4];
                    bf[nt][1] = sBb[nb * KP + kk + t4 + 4];
                }
#pragma unroll
                for (int mt = 0; mt < 4; mt++)
#pragma unroll
                    for (int nt = 0; nt < 4; nt++) {
                        mma_tf32(c[mt][nt], af[mt][0].x, af[mt][1].x, af[mt][2].x, af[mt][3].x,
                                 bf[nt][0].x, bf[nt][1].x);
                        mma_tf32(c[mt][nt], af[mt][0].x, af[mt][1].x, af[mt][2].x, af[mt][3].x,
                                 bf[nt][0].y, bf[nt][1].y);
                        mma_tf32(c[mt][nt], af[mt][0].y, af[mt][1].y, af[mt][2].y, af[mt][3].y,
                                 bf[nt][0].x, bf[nt][1].x);
                    }
            }
        }

        if (kb + 1 < NKB) {
            uint2* sAb = sA + ((kb + 1) & 1) * BK * MP;
            uint2* sBb = sB + ((kb + 1) & 1) * BN * KP;
#pragma unroll
            for (int cI = 0; cI < 4; cI++) {
                const float va[4] = {pa[cI].x, pa[cI].y, pa[cI].z, pa[cI].w};
                const float vb[4] = {pb[cI].x, pb[cI].y, pb[cI].z, pb[cI].w};
#pragma unroll
                for (int e = 0; e < 4; e++)
                    sAb[(kq + cI * 4 + e) * MP + lr] = split_tf32(va[e]);
                const uint2 s0 = split_tf32(vb[0]), s1 = split_tf32(vb[1]);
                const uint2 s2 = split_tf32(vb[2]), s3 = split_tf32(vb[3]);
                *(uint4*)&sBb[lr * KP + kq + cI * 4]     = make_uint4(s0.x, s0.y, s1.x, s1.y);
                *(uint4*)&sBb[lr * KP + kq + cI * 4 + 2] = make_uint4(s2.x, s2.y, s3.x, s3.y);
            }
        }
        __syncthreads();
    }

    // Store C tile.
#pragma unroll
    for (int mt = 0; mt < 4; mt++) {
        const int row0 = m0 + wm * 64 + mt * 16 + g8;
#pragma unroll
        for (int nt = 0; nt < 4; nt++) {
            const int col = n0 + wn * 32 + nt * 8 + t4 * 2;
            float2 lo = make_float2(c[mt][nt][0], c[mt][nt][1]);
            float2 hi = make_float2(c[mt][nt][2], c[mt][nt][3]);
            *(float2*)&g_w[(size_t)row0 * GG + col] = lo;
            *(float2*)&g_w[(size_t)(row0 + 8) * GG + col] = hi;
        }
    }

    // ---- Fused stats epilogue: per-column sum/sumsq over this tile's 128 rows ----
    {
        float2* scr = (float2*)sm2;   // [128 cols][16 slots] = 16KB
        __syncthreads();
        const int slot = wm * 8 + g8;
#pragma unroll
        for (int nt = 0; nt < 4; nt++) {
#pragma unroll
            for (int e = 0; e < 2; e++) {
                const int col = wn * 32 + nt * 8 + t4 * 2 + e;
                float sv = 0.0f, qv = 0.0f;
#pragma unroll
                for (int mt = 0; mt < 4; mt++) {
                    const float v0 = c[mt][nt][e];
                    const float v1 = c[mt][nt][e + 2];
                    sv += v0 + v1;
                    qv = fmaf(v0, v0, qv);
                    qv = fmaf(v1, v1, qv);
                }
                scr[col * 16 + slot] = make_float2(sv, qv);
            }
        }
        __syncthreads();
        if (tid < 128) {
            float sv = 0.0f, qv = 0.0f;
#pragma unroll
            for (int sl = 0; sl < 16; sl++) {
                const float2 v = scr[tid * 16 + sl];
                sv += v.x;
                qv += v.y;
            }
            g_psum[(size_t)blockIdx.y * GG + n0 + tid]   = sv;
            g_psumsq[(size_t)blockIdx.y * GG + n0 + tid] = qv;
        }
    }
}

// ---------------- finalize ----------------
__global__ void finalize_kernel(const float* __restrict__ gamma,
                                const float* __restrict__ beta) {
    const int g = blockIdx.x * blockDim.x + threadIdx.x;
    if (g >= GG) return;
    float s = 0.0f, q = 0.0f;
    for (int p = 0; p < NSTAT; p++) {
        s += g_psum[(size_t)p * GG + g];
        q += g_psumsq[(size_t)p * GG + g];
    }
    const float inv = 1.0f / (float)MM;
    const float mean = s * inv;
    const float var  = q * inv - mean * mean;
    const float sc   = gamma[g] * rsqrtf(var + 1e-5f);
    g_scale[g] = sc;
    g_shift[g] = beta[g] - mean * sc;
}

// ---------------- recurrence: two independent 64-CTA groups (fwd / bwd) -------------
// R14 structure (proven 9464us) with ONE change: the GPU-scope fence pair is
// executed by tid0 only (after __syncthreads), not by all 256 threads.
// Canonical release pattern: stores -> syncthreads -> tid0 fence -> atomic.
__global__ void __launch_bounds__(256, 1) recur_kernel(const float* __restrict__ U,
                                                       float* __restrict__ outp, int layer) {
    extern __shared__ float sm[];
    float* u_sm = sm;                                       // [1024][32] 128KB (a/z interleaved)
    float* h_sm = sm + 1024 * 32;                           // [1024][16]  64KB
    unsigned long long* p_sm =
        (unsigned long long*)(sm + 1024 * 32 + 1024 * 16);  // [16][16][17] 34KB (padded)
    unsigned long long* mbars = p_sm + 16 * 16 * 17;        // 4 slice mbarriers

    const int tid = threadIdx.x;
    const int b = blockIdx.x;
    const int group = b >> 6;
    const int j0 = (b & 63) * 16;
    const uint32_t mbar0 = smem_u32(mbars);
    const uint32_t h_smem_base = smem_u32(h_sm);

    uint32_t rank;
    asm("mov.u32 %0, %%cluster_ctarank;" : "=r"(rank));

    // Load U interleaved: col 2g' = a-row U[j0+g'], col 2g'+1 = z-row U[HH+j0+g'].
    for (int idx = tid; idx < 32 * 1024; idx += 256) {
        const int g = idx >> 10;
        const int k = idx & 1023;
        const int grow = (g < 16) ? (j0 + g) : (HH + j0 + (g - 16));
        const int col = (g < 16) ? (2 * g) : (2 * (g - 16) + 1);
        u_sm[k * 32 + col] = U[(size_t)grow * HH + k];
    }

    if (tid == 32) {
#pragma unroll
        for (int q = 0; q < 4; q++)
            asm volatile("mbarrier.init.shared.b64 [%0], %1;"
                         :: "r"(mbar0 + 8 * q), "r"(1) : "memory");
    }
    __syncthreads();
    asm volatile("barrier.cluster.arrive.aligned;" ::: "memory");
    asm volatile("barrier.cluster.wait.aligned;" ::: "memory");

    const int warp = tid >> 5, lane = tid & 31;
    const int ks2 = lane >> 4;                // 0..1
    const int sg = (lane >> 2) & 3;           // seq group: seqs sg*4..+3
    const int jg = lane & 3;                  // j group: js jg*4..+3
    const int kbase = warp * 128 + ks2;
    const int split = warp * 2 + ks2;
    const uint32_t my_mbar = mbar0 + 8 * (warp >> 1);

    const int sl = tid >> 4;                  // gating: seq-in-group 0..15
    const int jl = tid & 15;                  // gating: j-in-CTA 0..15
    const int jglob = j0 + jl;
    const int sglob = group * 16 + sl;
    const float sa_a = g_scale[jglob],      tb_a = g_shift[jglob];
    const float sa_z = g_scale[HH + jglob], tb_z = g_shift[HH + jglob];
    const float* wba = g_w + (size_t)sglob * TT * GG + jglob;
    const float* wbz = wba + HH;
    unsigned* mybar = &g_bars[group * 32];

    for (int t = 0; t < TT; t++) {
        // Per-slice expect_tx + this CTA's cooperative multicast slice (16KB).
        if (tid == 0) {
#pragma unroll
            for (int q = 0; q < 4; q++)
                asm volatile("mbarrier.arrive.expect_tx.shared.b64 _, [%0], %1;"
                             :: "r"(mbar0 + 8 * q), "r"(QB) : "memory");
            const char* src = (const char*)&g_hT2[group][t & 1][0] + rank * QB;
            asm volatile(
                "cp.async.bulk.shared::cluster.global.mbarrier::complete_tx::bytes"
                ".multicast::cluster [%0], [%1], %2, [%3], %4;"
                :: "r"(h_smem_base + rank * QB), "l"(src), "r"(QB),
                   "r"(mbar0 + 8 * rank), "h"((unsigned short)0xF) : "memory");
        }

        // Prefetch w gates (DRAM latency overlaps TMA wait).
        const float wa = __ldg(wba + (size_t)t * GG);
        const float wz = __ldg(wbz + (size_t)t * GG);

        mbar_wait(my_mbar, t & 1);

        unsigned long long acc[4][4];
#pragma unroll
        for (int s = 0; s < 4; s++)
#pragma unroll
            for (int p = 0; p < 4; p++) acc[s][p] = 0ull;

        const float* hp = h_sm + (size_t)kbase * 16 + sg * 4;
        const float* up = u_sm + (size_t)kbase * 32 + jg * 8;
#pragma unroll 8
        for (int i = 0; i < 64; i++) {
            const float4 h4 = *(const float4*)hp;
            unsigned long long hh0 = bcast2(h4.x), hh1 = bcast2(h4.y);
            unsigned long long hh2 = bcast2(h4.z), hh3 = bcast2(h4.w);
            const ulonglong2 ua = *(const ulonglong2*)up;
            const ulonglong2 ub = *(const ulonglong2*)(up + 4);
            ffma2(acc[0][0], ua.x, hh0); ffma2(acc[0][1], ua.y, hh0);
            ffma2(acc[0][2], ub.x, hh0); ffma2(acc[0][3], ub.y, hh0);
            ffma2(acc[1][0], ua.x, hh1); ffma2(acc[1][1], ua.y, hh1);
            ffma2(acc[1][2], ub.x, hh1); ffma2(acc[1][3], ub.y, hh1);
            ffma2(acc[2][0], ua.x, hh2); ffma2(acc[2][1], ua.y, hh2);
            ffma2(acc[2][2], ub.x, hh2); ffma2(acc[2][3], ub.y, hh2);
            ffma2(acc[3][0], ua.x, hh3); ffma2(acc[3][1], ua.y, hh3);
            ffma2(acc[3][2], ub.x, hh3); ffma2(acc[3][3], ub.y, hh3);
            hp += 32;   // k += 2 rows of 16
            up += 64;   // k += 2 rows of 32
        }

        // Partials: p_sm[split][seq][j], j pair = (a_j, z_j). Padded stride 17.
#pragma unroll
        for (int s = 0; s < 4; s++)
#pragma unroll
            for (int p = 0; p < 4; p++)
                p_sm[((size_t)split * 16 + sg * 4 + s) * 17 + jg * 4 + p] = acc[s][p];
        __syncthreads();

        // Fused reduce + gating: thread (sl, jl).
        float asum = 0.0f, zsum = 0.0f;
#pragma unroll
        for (int sp = 0; sp < 16; sp++) {
            const float2 v = unpack2(p_sm[((size_t)sp * 16 + sl) * 17 + jl]);
            asum += v.x;
            zsum += v.y;
        }
        const float aval = asum + fmaf(wa, sa_a, tb_a);
        const float zlin = zsum + fmaf(wz, sa_z, tb_z);
        const float zg = 1.0f / (1.0f + expf(-zlin));
        const float hprev = h_sm[jglob * 16 + sl];
        const float ar = aval > 0.0f ? aval : 0.0f;
        const float hnew = fmaf(zg, hprev - ar, ar);

        g_hT2[group][(t + 1) & 1][jglob * 16 + sl] = hnew;

        // Release: all threads' h stores ordered to tid0 by syncthreads; tid0
        // alone executes the GPU-scope + async-proxy fences, then the arrival.
        __syncthreads();
        if (tid == 0) {
            __threadfence();
            asm volatile("fence.proxy.async;" ::: "memory");
            atomicAdd(mybar, 1u);
        }

        // Output stores overlapped with barrier window.
        if (layer == 0) {
            g_hs0[((size_t)(sglob * TT) + t) * HH + jglob] = hnew;
        } else {
            if (sglob < BB)
                outp[((size_t)(sglob * TT) + t) * GG + jglob] = hnew;
            else
                outp[((size_t)((sglob - BB) * TT) + (TT - 1 - t)) * GG + HH + jglob] = hnew;
        }

        if (tid == 0) {
            const unsigned tgt = 64u * (unsigned)(t + 1);
            while (*(volatile unsigned*)mybar < tgt) {}
            __threadfence();
        }
        // No trailing __syncthreads (proven safe in R14): non-tid0 warps go
        // straight to the next step's parity mbar_wait.
    }

    asm volatile("barrier.cluster.arrive.aligned;" ::: "memory");
    asm volatile("barrier.cluster.wait.aligned;" ::: "memory");
}

// ---------------- host launcher ----------------
extern "C" void kernel_launch(void* const* d_in, const int* in_sizes, int n_in,
                              void* d_out, int out_size) {
    const float* x  = (const float*)d_in[0];
    const float* w0 = (const float*)d_in[1];
    const float* u0 = (const float*)d_in[2];
    const float* g0 = (const float*)d_in[3];
    const float* b0 = (const float*)d_in[4];
    const float* w1 = (const float*)d_in[5];
    const float* u1 = (const float*)d_in[6];
    const float* g1 = (const float*)d_in[7];
    const float* b1 = (const float*)d_in[8];
    float* outp = (float*)d_out;

    // u 128KB + h 64KB + partials 16*16*17*8 + mbars
    const int rsmem = (1024 * 32 + 1024 * 16) * 4 + 16 * 16 * 17 * 8 + 64;
    cudaFuncSetAttribute(recur_kernel, cudaFuncAttributeMaxDynamicSharedMemorySize, rsmem);

    const int gsmem = 2 * (BK * MP + BN * KP) * sizeof(uint2);
    cudaFuncSetAttribute(gemm_tc<FF, 0>, cudaFuncAttributeMaxDynamicSharedMemorySize, gsmem);
    cudaFuncSetAttribute(gemm_tc<GG, 1>, cudaFuncAttributeMaxDynamicSharedMemorySize, gsmem);

    const dim3 ggrid(GG / BN, MM / BM);

    cudaLaunchConfig_t cfg = {};
    cfg.gridDim = dim3(NC, 1, 1);
    cfg.blockDim = dim3(256, 1, 1);
    cfg.dynamicSmemBytes = rsmem;
    cudaLaunchAttribute attrs[1];
    attrs[0].id = cudaLaunchAttributeClusterDimension;
    attrs[0].val.clusterDim.x = CLS;
    attrs[0].val.clusterDim.y = 1;
    attrs[0].val.clusterDim.z = 1;
    cfg.attrs = attrs;
    cfg.numAttrs = 1;

    // Layer 0: harness memset(1), reset(2), gemm(3), finalize(4), recur(5)
    // -> ncu -s 5 -c 1 captures recur_kernel.
    reset_kernel<<<256, 256>>>();
    gemm_tc<FF, 0><<<ggrid, 256, gsmem>>>(x, w0);
    finalize_kernel<<<8, 256>>>(g0, b0);
    cudaLaunchKernelEx(&cfg, recur_kernel, (const float*)u0, (float*)nullptr, 0);

    // Layer 1
    reset_kernel<<<256, 256>>>();
    gemm_tc<GG, 1><<<ggrid, 256, gsmem>>>(nullptr, w1);
    finalize_kernel<<<8, 256>>>(g1, b1);
    cudaLaunchKernelEx(&cfg, recur_kernel, (const float*)u1, outp, 1);
}

// round 16
// speedup vs baseline: 1.0289x; 1.0289x over previous
#include <cuda_runtime.h>
#include <math.h>
#include <stdint.h>

// Problem constants
#define TT 500
#define BB 16
#define SS 32          // 2*B sequences
#define FF 512
#define HH 1024
#define GG 2048        // 2*H gates
#define MM 16000       // SS*TT rows
#define NC 128         // persistent CTAs (2 groups of 64)
#define NSTAT 125      // stats partial blocks (one per gemm row-tile)
#define CLS 4          // cluster size for h multicast
#define QB 16384       // 64KB group h / 4 slices

// GEMM tiling
#define BM 128
#define BN 128
#define BK 32
#define MP 132
#define KP 36

// ---------------- device scratch ----------------
__device__ float    g_w[(size_t)SS * TT * GG];
__device__ float    g_hs0[(size_t)SS * TT * HH];
__device__ float    g_hT2[2][2][1024 * 16];         // [group][slot][k][16 seq]
__device__ float    g_psum[NSTAT * GG];
__device__ float    g_psumsq[NSTAT * GG];
__device__ float    g_scale[GG];
__device__ float    g_shift[GG];
__device__ unsigned g_bars[64];                     // per-group counters, 128B apart

// ---------------- reset ----------------
__global__ void reset_kernel() {
    int idx = blockIdx.x * blockDim.x + threadIdx.x;
    if (idx < 2 * 2 * 1024 * 16) ((float*)g_hT2)[idx] = 0.0f;
    if (idx < 64) g_bars[idx] = 0u;
}

// ---------------- tf32 helpers ----------------
__device__ __forceinline__ uint2 split_tf32(float v) {
    uint32_t hi;
    asm("cvt.rna.tf32.f32 %0, %1;" : "=r"(hi) : "f"(v));
    float r = v - __uint_as_float(hi);
    uint32_t lo;
    asm("cvt.rna.tf32.f32 %0, %1;" : "=r"(lo) : "f"(r));
    return make_uint2(hi, lo);
}

__device__ __forceinline__ void mma_tf32(float c[4],
                                         uint32_t a0, uint32_t a1, uint32_t a2, uint32_t a3,
                                         uint32_t b0, uint32_t b1) {
    asm volatile(
        "mma.sync.aligned.m16n8k8.row.col.f32.tf32.tf32.f32 "
        "{%0,%1,%2,%3}, {%4,%5,%6,%7}, {%8,%9}, {%0,%1,%2,%3};"
        : "+f"(c[0]), "+f"(c[1]), "+f"(c[2]), "+f"(c[3])
        : "r"(a0), "r"(a1), "r"(a2), "r"(a3), "r"(b0), "r"(b1));
}

// ---------------- f32x2 helpers ----------------
__device__ __forceinline__ void ffma2(unsigned long long& c, unsigned long long a,
                                      unsigned long long b) {
    asm("fma.rn.f32x2 %0, %1, %2, %0;" : "+l"(c) : "l"(a), "l"(b));
}
__device__ __forceinline__ unsigned long long bcast2(float x) {
    unsigned long long r;
    unsigned xi = __float_as_uint(x);
    asm("mov.b64 %0, {%1, %1};" : "=l"(r) : "r"(xi));
    return r;
}
__device__ __forceinline__ float2 unpack2(unsigned long long v) {
    unsigned lo, hi;
    asm("mov.b64 {%0, %1}, %2;" : "=r"(lo), "=r"(hi) : "l"(v));
    return make_float2(__uint_as_float(lo), __uint_as_float(hi));
}

__device__ __forceinline__ uint32_t smem_u32(const void* p) {
    uint32_t a;
    asm("{ .reg .u64 t; cvta.to.shared.u64 t, %1; cvt.u32.u64 %0, t; }" : "=r"(a) : "l"(p));
    return a;
}

__device__ __forceinline__ void mbar_wait(uint32_t mbar, uint32_t parity) {
    asm volatile(
        "{\n\t.reg .pred P;\n\t"
        "W%=:\n\t"
        "mbarrier.try_wait.parity.acquire.cta.shared::cta.b64 P, [%0], %1;\n\t"
        "@!P bra W%=;\n\t}"
        :: "r"(mbar), "r"(parity) : "memory");
}

// ---------------- tensor-core GEMM (3xTF32) + fused stats epilogue ----------------
template <int K, int LAYER>
__global__ void __launch_bounds__(256) gemm_tc(const float* __restrict__ X,
                                               const float* __restrict__ Wt) {
    extern __shared__ uint2 sm2[];
    uint2* sA = sm2;
    uint2* sB = sm2 + 2 * BK * MP;

    const int tid = threadIdx.x;
    const int m0 = blockIdx.y * BM;
    const int n0 = blockIdx.x * BN;

    const int lr = tid >> 1;
    const int kq = (tid & 1) * 16;

    const int m = m0 + lr;
    const int s = m / TT;
    const int t = m - s * TT;
    const float* aLo;
    const float* aHi = nullptr;
    if (LAYER == 0) {
        aLo = (s < BB) ? X + (size_t)(s * TT + t) * FF
                       : X + (size_t)((s - BB) * TT + (TT - 1 - t)) * FF;
    } else {
        const int rowLo = (s < BB) ? (s * TT + t) : ((s - BB) * TT + (TT - 1 - t));
        const int rowHi = (s < BB) ? ((s + BB) * TT + (TT - 1 - t)) : (s * TT + t);
        aLo = g_hs0 + (size_t)rowLo * HH;
        aHi = g_hs0 + (size_t)rowHi * HH - HH;
    }
    const float* bPtr = Wt + (size_t)(n0 + lr) * K;

    const int wid = tid >> 5, lane = tid & 31;
    const int wm = wid >> 2, wn = wid & 3;
    const int g8 = lane >> 2, t4 = lane & 3;

    float c[4][4][4];
#pragma unroll
    for (int i = 0; i < 4; i++)
#pragma unroll
        for (int j = 0; j < 4; j++)
#pragma unroll
            for (int e = 0; e < 4; e++) c[i][j][e] = 0.0f;

    float4 pa[4], pb[4];
    const int NKB = K / BK;

    {
#pragma unroll
        for (int cI = 0; cI < 4; cI++) {
            const int kk = kq + cI * 4;
            const float* ap = (LAYER == 0) ? aLo : ((kk < HH) ? aLo : aHi);
            pa[cI] = *(const float4*)(ap + kk);
            pb[cI] = *(const float4*)(bPtr + kk);
        }
        uint2* sAb = sA;
        uint2* sBb = sB;
#pragma unroll
        for (int cI = 0; cI < 4; cI++) {
            const float va[4] = {pa[cI].x, pa[cI].y, pa[cI].z, pa[cI].w};
            const float vb[4] = {pb[cI].x, pb[cI].y, pb[cI].z, pb[cI].w};
#pragma unroll
            for (int e = 0; e < 4; e++)
                sAb[(kq + cI * 4 + e) * MP + lr] = split_tf32(va[e]);
            const uint2 s0 = split_tf32(vb[0]), s1 = split_tf32(vb[1]);
            const uint2 s2 = split_tf32(vb[2]), s3 = split_tf32(vb[3]);
            *(uint4*)&sBb[lr * KP + kq + cI * 4]     = make_uint4(s0.x, s0.y, s1.x, s1.y);
            *(uint4*)&sBb[lr * KP + kq + cI * 4 + 2] = make_uint4(s2.x, s2.y, s3.x, s3.y);
        }
    }
    __syncthreads();

    for (int kb = 0; kb < NKB; kb++) {
        if (kb + 1 < NKB) {
            const int k0 = (kb + 1) * BK;
#pragma unroll
            for (int cI = 0; cI < 4; cI++) {
                const int kk = k0 + kq + cI * 4;
                const float* ap = (LAYER == 0) ? aLo : ((kk < HH) ? aLo : aHi);
                pa[cI] = *(const float4*)(ap + kk);
                pb[cI] = *(const float4*)(bPtr + kk);
            }
        }

        {
            uint2* sAb = sA + (kb & 1) * BK * MP;
            uint2* sBb = sB + (kb & 1) * BN * KP;
#pragma unroll
            for (int k8 = 0; k8 < 4; k8++) {
                const int kk = k8 * 8;
                uint2 af[4][4];
#pragma unroll
                for (int mt = 0; mt < 4; mt++) {
                    const int mb = wm * 64 + mt * 16 + g8;
                    af[mt][0] = sAb[(kk + t4) * MP + mb];
                    af[mt][1] = sAb[(kk + t4) * MP + mb + 8];
                    af[mt][2] = sAb[(kk + t4 + 4) * MP + mb];
                    af[mt][3] = sAb[(kk + t4 + 4) * MP + mb + 8];
                }
                uint2 bf[4][2];
#pragma unroll
                for (int nt = 0; nt < 4; nt++) {
                    const int nb = wn * 32 + nt * 8 + g8;
                    bf[nt][0] = sBb[nb * KP + kk + t4];
                    bf[nt][1] = sBb[nb * KP + kk + t4 + 4];
                }
#pragma unroll
                for (int mt = 0; mt < 4; mt++)
#pragma unroll
                    for (int nt = 0; nt < 4; nt++) {
                        mma_tf32(c[mt][nt], af[mt][0].x, af[mt][1].x, af[mt][2].x, af[mt][3].x,
                                 bf[nt][0].x, bf[nt][1].x);
                        mma_tf32(c[mt][nt], af[mt][0].x, af[mt][1].x, af[mt][2].x, af[mt][3].x,
                                 bf[nt][0].y, bf[nt][1].y);
                        mma_tf32(c[mt][nt], af[mt][0].y, af[mt][1].y, af[mt][2].y, af[mt][3].y,
                                 bf[nt][0].x, bf[nt][1].x);
                    }
            }
        }

        if (kb + 1 < NKB) {
            uint2* sAb = sA + ((kb + 1) & 1) * BK * MP;
            uint2* sBb = sB + ((kb + 1) & 1) * BN * KP;
#pragma unroll
            for (int cI = 0; cI < 4; cI++) {
                const float va[4] = {pa[cI].x, pa[cI].y, pa[cI].z, pa[cI].w};
                const float vb[4] = {pb[cI].x, pb[cI].y, pb[cI].z, pb[cI].w};
#pragma unroll
                for (int e = 0; e < 4; e++)
                    sAb[(kq + cI * 4 + e) * MP + lr] = split_tf32(va[e]);
                const uint2 s0 = split_tf32(vb[0]), s1 = split_tf32(vb[1]);
                const uint2 s2 = split_tf32(vb[2]), s3 = split_tf32(vb[3]);
                *(uint4*)&sBb[lr * KP + kq + cI * 4]     = make_uint4(s0.x, s0.y, s1.x, s1.y);
                *(uint4*)&sBb[lr * KP + kq + cI * 4 + 2] = make_uint4(s2.x, s2.y, s3.x, s3.y);
            }
        }
        __syncthreads();
    }

    // Store C tile.
#pragma unroll
    for (int mt = 0; mt < 4; mt++) {
        const int row0 = m0 + wm * 64 + mt * 16 + g8;
#pragma unroll
        for (int nt = 0; nt < 4; nt++) {
            const int col = n0 + wn * 32 + nt * 8 + t4 * 2;
            float2 lo = make_float2(c[mt][nt][0], c[mt][nt][1]);
            float2 hi = make_float2(c[mt][nt][2], c[mt][nt][3]);
            *(float2*)&g_w[(size_t)row0 * GG + col] = lo;
            *(float2*)&g_w[(size_t)(row0 + 8) * GG + col] = hi;
        }
    }

    // ---- Fused stats epilogue ----
    {
        float2* scr = (float2*)sm2;   // [128 cols][16 slots] = 16KB
        __syncthreads();
        const int slot = wm * 8 + g8;
#pragma unroll
        for (int nt = 0; nt < 4; nt++) {
#pragma unroll
            for (int e = 0; e < 2; e++) {
                const int col = wn * 32 + nt * 8 + t4 * 2 + e;
                float sv = 0.0f, qv = 0.0f;
#pragma unroll
                for (int mt = 0; mt < 4; mt++) {
                    const float v0 = c[mt][nt][e];
                    const float v1 = c[mt][nt][e + 2];
                    sv += v0 + v1;
                    qv = fmaf(v0, v0, qv);
                    qv = fmaf(v1, v1, qv);
                }
                scr[col * 16 + slot] = make_float2(sv, qv);
            }
        }
        __syncthreads();
        if (tid < 128) {
            float sv = 0.0f, qv = 0.0f;
#pragma unroll
            for (int sl = 0; sl < 16; sl++) {
                const float2 v = scr[tid * 16 + sl];
                sv += v.x;
                qv += v.y;
            }
            g_psum[(size_t)blockIdx.y * GG + n0 + tid]   = sv;
            g_psumsq[(size_t)blockIdx.y * GG + n0 + tid] = qv;
        }
    }
}

// ---------------- finalize ----------------
__global__ void finalize_kernel(const float* __restrict__ gamma,
                                const float* __restrict__ beta) {
    const int g = blockIdx.x * blockDim.x + threadIdx.x;
    if (g >= GG) return;
    float s = 0.0f, q = 0.0f;
    for (int p = 0; p < NSTAT; p++) {
        s += g_psum[(size_t)p * GG + g];
        q += g_psumsq[(size_t)p * GG + g];
    }
    const float inv = 1.0f / (float)MM;
    const float mean = s * inv;
    const float var  = q * inv - mean * mean;
    const float sc   = gamma[g] * rsqrtf(var + 1e-5f);
    g_scale[g] = sc;
    g_shift[g] = beta[g] - mean * sc;
}

// ---------------- recurrence: two independent 64-CTA groups (fwd / bwd) -------------
// Exact R14 release sequence (measured best: all-thread fences -> syncthreads
// -> tid0 atomic) + w-gate loads software-pipelined ONE FULL STEP ahead so
// their DRAM latency/variance leaves the critical path.
__global__ void __launch_bounds__(256, 1) recur_kernel(const float* __restrict__ U,
                                                       float* __restrict__ outp, int layer) {
    extern __shared__ float sm[];
    float* u_sm = sm;                                       // [1024][32] 128KB (a/z interleaved)
    float* h_sm = sm + 1024 * 32;                           // [1024][16]  64KB
    unsigned long long* p_sm =
        (unsigned long long*)(sm + 1024 * 32 + 1024 * 16);  // [16][16][17] 34KB (padded)
    unsigned long long* mbars = p_sm + 16 * 16 * 17;        // 4 slice mbarriers

    const int tid = threadIdx.x;
    const int b = blockIdx.x;
    const int group = b >> 6;
    const int j0 = (b & 63) * 16;
    const uint32_t mbar0 = smem_u32(mbars);
    const uint32_t h_smem_base = smem_u32(h_sm);

    uint32_t rank;
    asm("mov.u32 %0, %%cluster_ctarank;" : "=r"(rank));

    // Load U interleaved: col 2g' = a-row U[j0+g'], col 2g'+1 = z-row U[HH+j0+g'].
    for (int idx = tid; idx < 32 * 1024; idx += 256) {
        const int g = idx >> 10;
        const int k = idx & 1023;
        const int grow = (g < 16) ? (j0 + g) : (HH + j0 + (g - 16));
        const int col = (g < 16) ? (2 * g) : (2 * (g - 16) + 1);
        u_sm[k * 32 + col] = U[(size_t)grow * HH + k];
    }

    if (tid == 32) {
#pragma unroll
        for (int q = 0; q < 4; q++)
            asm volatile("mbarrier.init.shared.b64 [%0], %1;"
                         :: "r"(mbar0 + 8 * q), "r"(1) : "memory");
    }
    __syncthreads();
    asm volatile("barrier.cluster.arrive.aligned;" ::: "memory");
    asm volatile("barrier.cluster.wait.aligned;" ::: "memory");

    const int warp = tid >> 5, lane = tid & 31;
    const int ks2 = lane >> 4;                // 0..1
    const int sg = (lane >> 2) & 3;           // seq group: seqs sg*4..+3
    const int jg = lane & 3;                  // j group: js jg*4..+3
    const int kbase = warp * 128 + ks2;
    const int split = warp * 2 + ks2;
    const uint32_t my_mbar = mbar0 + 8 * (warp >> 1);

    const int sl = tid >> 4;                  // gating: seq-in-group 0..15
    const int jl = tid & 15;                  // gating: j-in-CTA 0..15
    const int jglob = j0 + jl;
    const int sglob = group * 16 + sl;
    const float sa_a = g_scale[jglob],      tb_a = g_shift[jglob];
    const float sa_z = g_scale[HH + jglob], tb_z = g_shift[HH + jglob];
    const float* wba = g_w + (size_t)sglob * TT * GG + jglob;
    const float* wbz = wba + HH;
    unsigned* mybar = &g_bars[group * 32];

    // w-gate pipeline: load step-0 values up front.
    float wa_cur = __ldg(wba);
    float wz_cur = __ldg(wbz);

    for (int t = 0; t < TT; t++) {
        // Per-slice expect_tx + this CTA's cooperative multicast slice (16KB).
        if (tid == 0) {
#pragma unroll
            for (int q = 0; q < 4; q++)
                asm volatile("mbarrier.arrive.expect_tx.shared.b64 _, [%0], %1;"
                             :: "r"(mbar0 + 8 * q), "r"(QB) : "memory");
            const char* src = (const char*)&g_hT2[group][t & 1][0] + rank * QB;
            asm volatile(
                "cp.async.bulk.shared::cluster.global.mbarrier::complete_tx::bytes"
                ".multicast::cluster [%0], [%1], %2, [%3], %4;"
                :: "r"(h_smem_base + rank * QB), "l"(src), "r"(QB),
                   "r"(mbar0 + 8 * rank), "h"((unsigned short)0xF) : "memory");
        }

        mbar_wait(my_mbar, t & 1);

        // Prefetch NEXT step's w gates: ~full step of latency cover.
        float wa_nxt = 0.0f, wz_nxt = 0.0f;
        if (t + 1 < TT) {
            wa_nxt = __ldg(wba + (size_t)(t + 1) * GG);
            wz_nxt = __ldg(wbz + (size_t)(t + 1) * GG);
        }

        unsigned long long acc[4][4];
#pragma unroll
        for (int s = 0; s < 4; s++)
#pragma unroll
            for (int p = 0; p < 4; p++) acc[s][p] = 0ull;

        const float* hp = h_sm + (size_t)kbase * 16 + sg * 4;
        const float* up = u_sm + (size_t)kbase * 32 + jg * 8;
#pragma unroll 8
        for (int i = 0; i < 64; i++) {
            const float4 h4 = *(const float4*)hp;
            unsigned long long hh0 = bcast2(h4.x), hh1 = bcast2(h4.y);
            unsigned long long hh2 = bcast2(h4.z), hh3 = bcast2(h4.w);
            const ulonglong2 ua = *(const ulonglong2*)up;
            const ulonglong2 ub = *(const ulonglong2*)(up + 4);
            ffma2(acc[0][0], ua.x, hh0); ffma2(acc[0][1], ua.y, hh0);
            ffma2(acc[0][2], ub.x, hh0); ffma2(acc[0][3], ub.y, hh0);
            ffma2(acc[1][0], ua.x, hh1); ffma2(acc[1][1], ua.y, hh1);
            ffma2(acc[1][2], ub.x, hh1); ffma2(acc[1][3], ub.y, hh1);
            ffma2(acc[2][0], ua.x, hh2); ffma2(acc[2][1], ua.y, hh2);
            ffma2(acc[2][2], ub.x, hh2); ffma2(acc[2][3], ub.y, hh2);
            ffma2(acc[3][0], ua.x, hh3); ffma2(acc[3][1], ua.y, hh3);
            ffma2(acc[3][2], ub.x, hh3); ffma2(acc[3][3], ub.y, hh3);
            hp += 32;   // k += 2 rows of 16
            up += 64;   // k += 2 rows of 32
        }

        // Partials: p_sm[split][seq][j], j pair = (a_j, z_j). Padded stride 17.
#pragma unroll
        for (int s = 0; s < 4; s++)
#pragma unroll
            for (int p = 0; p < 4; p++)
                p_sm[((size_t)split * 16 + sg * 4 + s) * 17 + jg * 4 + p] = acc[s][p];
        __syncthreads();

        // Fused reduce + gating: thread (sl, jl).
        float asum = 0.0f, zsum = 0.0f;
#pragma unroll
        for (int sp = 0; sp < 16; sp++) {
            const float2 v = unpack2(p_sm[((size_t)sp * 16 + sl) * 17 + jl]);
            asum += v.x;
            zsum += v.y;
        }
        const float aval = asum + fmaf(wa_cur, sa_a, tb_a);
        const float zlin = zsum + fmaf(wz_cur, sa_z, tb_z);
        const float zg = 1.0f / (1.0f + expf(-zlin));
        const float hprev = h_sm[jglob * 16 + sl];
        const float ar = aval > 0.0f ? aval : 0.0f;
        const float hnew = fmaf(zg, hprev - ar, ar);

        g_hT2[group][(t + 1) & 1][jglob * 16 + sl] = hnew;

        // Publish h (R14-proven order), then group epoch barrier.
        __threadfence();
        asm volatile("fence.proxy.async;" ::: "memory");
        __syncthreads();
        if (tid == 0) atomicAdd(mybar, 1u);

        // Output stores overlapped with barrier window.
        if (layer == 0) {
            g_hs0[((size_t)(sglob * TT) + t) * HH + jglob] = hnew;
        } else {
            if (sglob < BB)
                outp[((size_t)(sglob * TT) + t) * GG + jglob] = hnew;
            else
                outp[((size_t)((sglob - BB) * TT) + (TT - 1 - t)) * GG + HH + jglob] = hnew;
        }

        if (tid == 0) {
            const unsigned tgt = 64u * (unsigned)(t + 1);
            while (*(volatile unsigned*)mybar < tgt) {}
            __threadfence();
        }
        // No trailing __syncthreads (proven safe in R14).

        wa_cur = wa_nxt;
        wz_cur = wz_nxt;
    }

    asm volatile("barrier.cluster.arrive.aligned;" ::: "memory");
    asm volatile("barrier.cluster.wait.aligned;" ::: "memory");
}

// ---------------- host launcher ----------------
extern "C" void kernel_launch(void* const* d_in, const int* in_sizes, int n_in,
                              void* d_out, int out_size) {
    const float* x  = (const float*)d_in[0];
    const float* w0 = (const float*)d_in[1];
    const float* u0 = (const float*)d_in[2];
    const float* g0 = (const float*)d_in[3];
    const float* b0 = (const float*)d_in[4];
    const float* w1 = (const float*)d_in[5];
    const float* u1 = (const float*)d_in[6];
    const float* g1 = (const float*)d_in[7];
    const float* b1 = (const float*)d_in[8];
    float* outp = (float*)d_out;

    // u 128KB + h 64KB + partials 16*16*17*8 + mbars
    const int rsmem = (1024 * 32 + 1024 * 16) * 4 + 16 * 16 * 17 * 8 + 64;
    cudaFuncSetAttribute(recur_kernel, cudaFuncAttributeMaxDynamicSharedMemorySize, rsmem);

    const int gsmem = 2 * (BK * MP + BN * KP) * sizeof(uint2);
    cudaFuncSetAttribute(gemm_tc<FF, 0>, cudaFuncAttributeMaxDynamicSharedMemorySize, gsmem);
    cudaFuncSetAttribute(gemm_tc<GG, 1>, cudaFuncAttributeMaxDynamicSharedMemorySize, gsmem);

    const dim3 ggrid(GG / BN, MM / BM);

    cudaLaunchConfig_t cfg = {};
    cfg.gridDim = dim3(NC, 1, 1);
    cfg.blockDim = dim3(256, 1, 1);
    cfg.dynamicSmemBytes = rsmem;
    cudaLaunchAttribute attrs[1];
    attrs[0].id = cudaLaunchAttributeClusterDimension;
    attrs[0].val.clusterDim.x = CLS;
    attrs[0].val.clusterDim.y = 1;
    attrs[0].val.clusterDim.z = 1;
    cfg.attrs = attrs;
    cfg.numAttrs = 1;

    // Layer 0: harness memset(1), reset(2), gemm(3), finalize(4), recur(5)
    // -> ncu -s 5 -c 1 captures recur_kernel.
    reset_kernel<<<256, 256>>>();
    gemm_tc<FF, 0><<<ggrid, 256, gsmem>>>(x, w0);
    finalize_kernel<<<8, 256>>>(g0, b0);
    cudaLaunchKernelEx(&cfg, recur_kernel, (const float*)u0, (float*)nullptr, 0);

    // Layer 1
    reset_kernel<<<256, 256>>>();
    gemm_tc<GG, 1><<<ggrid, 256, gsmem>>>(nullptr, w1);
    finalize_kernel<<<8, 256>>>(g1, b1);
    cudaLaunchKernelEx(&cfg, recur_kernel, (const float*)u1, outp, 1);
}